// round 10
// baseline (speedup 1.0000x reference)
#include <cuda_runtime.h>
#include <cuda_fp16.h>
#include <cstdint>
#include <cstddef>

#define DEVI static __device__ __forceinline__

namespace li {

constexpr int B = 32, T = 1024, IN = 1024, OUT = 1024;
constexpr int TT = 128;                 // time rows per tile (GEMM M)
constexpr int TO = 128;                 // out cols per CTA   (GEMM N)
constexpr int BKH = 64;                 // halves (=floats) per K slab
constexpr int SLABS = IN / BKH;         // 16
constexpr int TILES = T / TT;           // 8
constexpr int G = TILES * SLABS;        // 128 slabs per CTA

constexpr int STAGE_BYTES = (TT + TO) * 128;   // 32 KB (X 16K + W 16K, fp16)
constexpr int STG_STRIDE = 136;                // halves; conflict-free
constexpr int STAGING_OFF = 2 * STAGE_BYTES;   // 65536
constexpr int SMEM_DYN = STAGING_OFF + TT * STG_STRIDE * 2;  // 100352

__device__ __align__(16) __half g_Wh[(size_t)OUT * IN];  // 2MB W scratch only

DEVI uint32_t s2u(const void* p) {
  uint32_t a;
  asm("{ .reg .u64 t; cvta.to.shared.u64 t, %1; cvt.u32.u64 %0, t; }"
      : "=r"(a) : "l"(p));
  return a;
}
DEVI void cp16(uint32_t s, const void* g) {
  asm volatile("cp.async.cg.shared.global [%0], [%1], 16;" :: "r"(s), "l"(g)
               : "memory");
}
DEVI void cp_commit() { asm volatile("cp.async.commit_group;" ::: "memory"); }
DEVI void cp_wait0() { asm volatile("cp.async.wait_group 0;" ::: "memory"); }

DEVI void ldsm4(uint32_t* r, uint32_t a) {
  asm volatile("ldmatrix.sync.aligned.m8n8.x4.shared.b16 {%0,%1,%2,%3}, [%4];"
               : "=r"(r[0]), "=r"(r[1]), "=r"(r[2]), "=r"(r[3]) : "r"(a));
}
DEVI void mma16(float* c, const uint32_t* a, const uint32_t* b) {
  asm volatile(
      "mma.sync.aligned.m16n8k16.row.col.f32.f16.f16.f32 "
      "{%0,%1,%2,%3}, {%4,%5,%6,%7}, {%8,%9}, {%0,%1,%2,%3};"
      : "+f"(c[0]), "+f"(c[1]), "+f"(c[2]), "+f"(c[3])
      : "r"(a[0]), "r"(a[1]), "r"(a[2]), "r"(a[3]), "r"(b[0]), "r"(b[1]));
}
DEVI uint32_t packh2(float lo, float hi) {
  uint32_t d;
  asm("cvt.rn.f16x2.f32 %0, %1, %2;" : "=r"(d) : "f"(hi), "f"(lo));
  return d;
}
DEVI void sts128(uint32_t a, uint32_t r0, uint32_t r1, uint32_t r2,
                 uint32_t r3) {
  asm volatile("st.shared.v4.b32 [%0], {%1,%2,%3,%4};"
               :: "r"(a), "r"(r0), "r"(r1), "r"(r2), "r"(r3) : "memory");
}

// ---------------- tiny pre-pass: W fp32 -> fp16 scratch (4MB read) -----------
__global__ void __launch_bounds__(256) cvtw_kernel(const float4* __restrict__ W) {
  uint2* wo = reinterpret_cast<uint2*>(g_Wh);
  const int i = blockIdx.x * blockDim.x + threadIdx.x;  // grid covers exactly
  float4 v = W[i];
  __half2 a = __float22half2_rn({v.x, v.y});
  __half2 b = __float22half2_rn({v.z, v.w});
  uint2 u;
  u.x = *reinterpret_cast<unsigned*>(&a);
  u.y = *reinterpret_cast<unsigned*>(&b);
  wo[i] = u;
}

// ---------------- main fused: X cvt-in-producer + GEMM + scan ----------------
// 128 threads, 4 warps 2x2, warp tile 64x64, kc-pipelined fragments.
__global__ void __launch_bounds__(128, 2)
li_kernel(const float* __restrict__ X, const float* __restrict__ bias,
          const float* __restrict__ decay, float* __restrict__ out) {
  extern __shared__ __align__(16) char dsm[];
  const uint32_t sbase = s2u(dsm);

  const int tid = threadIdx.x;
  const int wid = tid >> 5;
  const int lane = tid & 31;
  const int bb = blockIdx.x >> 3;
  const int o0 = (blockIdx.x & 7) * TO;

  // ---- scan state ----
  const float dcy = decay[o0 + tid];
  const float omd = 1.0f - dcy;
  const float bo = bias[o0 + tid];
  float u = 0.f;

  // ---- W producer constants (cp.async, unchanged) ----
  const int lr = tid >> 3;
  const int lc = tid & 7;
  const uint32_t w_sw = (uint32_t)lr * 128 + (uint32_t)((lc ^ (lr & 7)) << 4);
  const __half* Wg = g_Wh + (size_t)(o0 + lr) * IN + lc * 8;

  // ---- X producer constants (LDG fp32 -> cvt -> STS fp16) ----
  // assignment a in {0,1}: row = (tid>>1) + 64a, half hc = tid&1 (32 floats)
  const int xrow0 = tid >> 1;
  const int hc = tid & 1;
  const float* Xg0 = X + ((size_t)bb * T + xrow0) * IN + hc * 32;

  // ---- mma constants ----
  const int warp_m = wid >> 1, warp_n = wid & 1;
  const int r = lane & 7;
  const int khA = lane >> 4;
  const int khB = (lane >> 3) & 1;
  const uint32_t aBase =
      (uint32_t)(warp_m * 64 + ((lane >> 3) & 1) * 8 + r) * 128;
  const uint32_t bBase =
      (uint32_t)(TT * 128) +
      (uint32_t)(warp_n * 64 + ((lane >> 4) << 3) + r) * 128;

  float acc[4][8][4];

  auto load_w = [&](int g) {
    const int t0o = (g >> 4) * 0;  // W has no t dependence
    (void)t0o;
    const int k0 = (g & 15) * BKH;
    const uint32_t wb =
        sbase + (uint32_t)(TT * 128) + (uint32_t)(g & 1) * STAGE_BYTES;
    const __half* Ws = Wg + k0;
#pragma unroll
    for (int i = 0; i < 8; ++i)
      cp16(wb + w_sw + (uint32_t)i * 2048, Ws + (size_t)i * 16 * IN);
  };
  auto ldg_x = [&](int g, int a, float4* buf) {
    const int t0 = (g >> 4) * TT;
    const int k0 = (g & 15) * BKH;
    const float4* src = reinterpret_cast<const float4*>(
        Xg0 + ((size_t)t0 + 64 * a) * IN + k0);
#pragma unroll
    for (int j = 0; j < 8; ++j) buf[j] = src[j];
  };
  auto sts_x = [&](int g, int a, const float4* buf) {
    const uint32_t xb = sbase + (uint32_t)(g & 1) * STAGE_BYTES;
    const int row = xrow0 + 64 * a;
#pragma unroll
    for (int j = 0; j < 4; ++j) {
      const uint32_t addr =
          xb + (uint32_t)row * 128 +
          (uint32_t)((((hc << 2) + j) ^ (row & 7)) << 4);
      sts128(addr, packh2(buf[2 * j].x, buf[2 * j].y),
             packh2(buf[2 * j].z, buf[2 * j].w),
             packh2(buf[2 * j + 1].x, buf[2 * j + 1].y),
             packh2(buf[2 * j + 1].z, buf[2 * j + 1].w));
    }
  };

  // prologue: slab 0 (W via cp.async, X converted synchronously)
  {
    float4 xb0[8];
    load_w(0);
    cp_commit();
    ldg_x(0, 0, xb0);
    sts_x(0, 0, xb0);
    ldg_x(0, 1, xb0);
    sts_x(0, 1, xb0);
  }

  int g = 0;
  for (int tile = 0; tile < TILES; ++tile) {
#pragma unroll
    for (int mf = 0; mf < 4; ++mf)
#pragma unroll
      for (int nf = 0; nf < 8; ++nf)
#pragma unroll
        for (int j = 0; j < 4; ++j) acc[mf][nf][j] = 0.f;

    for (int ks = 0; ks < SLABS; ++ks) {
      cp_wait0();       // W slab g arrived
      __syncthreads();  // + X STS for buffer g&1 drained
      const uint32_t sb = sbase + (uint32_t)(g & 1) * STAGE_BYTES;
      const bool more = (g + 1 < G);

      // preload kc=0 fragments
      uint32_t A[2][4][4], Bf[2][4][4];
      {
        const uint32_t swA = (uint32_t)((khA ^ r) << 4);
        const uint32_t swB = (uint32_t)((khB ^ r) << 4);
#pragma unroll
        for (int mf = 0; mf < 4; ++mf)
          ldsm4(A[0][mf], sb + aBase + (uint32_t)mf * 2048 + swA);
#pragma unroll
        for (int p = 0; p < 4; ++p)
          ldsm4(Bf[0][p], sb + bBase + (uint32_t)p * 2048 + swB);
      }

      float4 xbuf[8];
      if (more) {
        load_w(g + 1);
        cp_commit();
        ldg_x(g + 1, 0, xbuf);  // chunk A in flight during kc0/kc1
      }

#pragma unroll
      for (int kc = 0; kc < 4; ++kc) {
        const int pb = kc & 1;
        if (kc < 3) {
          const uint32_t swA = (uint32_t)(((2 * (kc + 1) + khA) ^ r) << 4);
          const uint32_t swB = (uint32_t)(((2 * (kc + 1) + khB) ^ r) << 4);
#pragma unroll
          for (int mf = 0; mf < 4; ++mf)
            ldsm4(A[pb ^ 1][mf], sb + aBase + (uint32_t)mf * 2048 + swA);
#pragma unroll
          for (int p = 0; p < 4; ++p)
            ldsm4(Bf[pb ^ 1][p], sb + bBase + (uint32_t)p * 2048 + swB);
        }
#pragma unroll
        for (int mf = 0; mf < 4; ++mf)
#pragma unroll
          for (int nf = 0; nf < 8; ++nf)
            mma16(acc[mf][nf], A[pb][mf], &Bf[pb][nf >> 1][(nf & 1) * 2]);
        if (kc == 1 && more) {
          sts_x(g + 1, 0, xbuf);   // consume chunk A
          ldg_x(g + 1, 1, xbuf);   // chunk B in flight during kc2/kc3
        }
      }
      if (more) sts_x(g + 1, 1, xbuf);  // chunk B (drained by next barrier)
      ++g;
    }

    // ---- epilogue: fragments -> fp16 staging [t][o] ----
    unsigned* stg_u = reinterpret_cast<unsigned*>(dsm + STAGING_OFF);
#pragma unroll
    for (int mf = 0; mf < 4; ++mf)
#pragma unroll
      for (int nf = 0; nf < 8; ++nf) {
        const int row = warp_m * 64 + mf * 16 + (lane >> 2);
        const int col = warp_n * 64 + nf * 8 + 2 * (lane & 3);
        stg_u[(row * STG_STRIDE + col) >> 1] =
            packh2(acc[mf][nf][0], acc[mf][nf][1]);
        stg_u[((row + 8) * STG_STRIDE + col) >> 1] =
            packh2(acc[mf][nf][2], acc[mf][nf][3]);
      }
    __syncthreads();

    // ---- fused leaky-integrator scan; carry u persists across tiles ----
    {
      const __half* sh = reinterpret_cast<const __half*>(dsm + STAGING_OFF);
      float* ob = out + ((size_t)bb * T + tile * TT) * OUT + o0 + tid;
#pragma unroll 8
      for (int t = 0; t < TT; ++t) {
        const float x = __half2float(sh[t * STG_STRIDE + tid]) + bo;
        u = fmaf(dcy, u, omd * x);
        ob[(size_t)t * OUT] = u;
      }
    }
  }
}

}  // namespace li

extern "C" void kernel_launch(void* const* d_in, const int* in_sizes, int n_in,
                              void* d_out, int out_size) {
  const float* X = (const float*)d_in[0];      // [B,T,IN]
  const float* W = (const float*)d_in[1];      // [OUT,IN]
  const float* bias = (const float*)d_in[2];   // [OUT]
  const float* decay = (const float*)d_in[3];  // [OUT]
  float* out = (float*)d_out;                  // [B,T,OUT]

  static bool init = false;
  if (!init) {
    cudaFuncSetAttribute(li::li_kernel,
                         cudaFuncAttributeMaxDynamicSharedMemorySize,
                         li::SMEM_DYN);
    init = true;
  }
  // W: OUT*IN/4 = 262144 float4 -> 1024 blocks x 256 threads
  li::cvtw_kernel<<<1024, 256>>>((const float4*)W);
  li::li_kernel<<<li::B * (li::OUT / li::TO), 128, li::SMEM_DYN>>>(
      X, bias, decay, out);
}

// round 11
// speedup vs baseline: 1.8705x; 1.8705x over previous
#include <cuda_runtime.h>
#include <cuda_fp16.h>
#include <cstdint>
#include <cstddef>

#define DEVI static __device__ __forceinline__

namespace li {

constexpr int B = 32, T = 1024, IN = 1024, OUT = 1024;
constexpr int TT = 128;                 // time rows per tile (GEMM M)
constexpr int TO = 128;                 // out cols per CTA   (GEMM N)
constexpr int BKH = 64;                 // halves per K slab (= one 128B row)
constexpr int SLABS = IN / BKH;         // 16
constexpr int TILES = T / TT;           // 8
constexpr int G = TILES * SLABS;        // 128 slabs per CTA

constexpr int STAGE_BYTES = (TT + TO) * 128;   // 32 KB (X 16K + W 16K, fp16)
constexpr int STG_STRIDE = 136;                // halves; conflict-free
constexpr int STAGING_OFF = 2 * STAGE_BYTES;   // 65536
constexpr int SMEM_DYN = STAGING_OFF + TT * STG_STRIDE * 2;  // 100352

__device__ __align__(16) __half g_Xh[(size_t)B * T * IN];   // 64MB scratch
__device__ __align__(16) __half g_Wh[(size_t)OUT * IN];     // 2MB scratch
__device__ int g_arr;   // grid barrier: 256 arrive + 256 consume, self-reset

DEVI uint32_t s2u(const void* p) {
  uint32_t a;
  asm("{ .reg .u64 t; cvta.to.shared.u64 t, %1; cvt.u32.u64 %0, t; }"
      : "=r"(a) : "l"(p));
  return a;
}
DEVI void cp16(uint32_t s, const void* g) {
  asm volatile("cp.async.cg.shared.global [%0], [%1], 16;" :: "r"(s), "l"(g)
               : "memory");
}
DEVI void cp_commit() { asm volatile("cp.async.commit_group;" ::: "memory"); }
DEVI void cp_wait0() { asm volatile("cp.async.wait_group 0;" ::: "memory"); }

DEVI void ldsm4(uint32_t* r, uint32_t a) {
  asm volatile("ldmatrix.sync.aligned.m8n8.x4.shared.b16 {%0,%1,%2,%3}, [%4];"
               : "=r"(r[0]), "=r"(r[1]), "=r"(r[2]), "=r"(r[3]) : "r"(a));
}
DEVI void mma16(float* c, const uint32_t* a, const uint32_t* b) {
  asm volatile(
      "mma.sync.aligned.m16n8k16.row.col.f32.f16.f16.f32 "
      "{%0,%1,%2,%3}, {%4,%5,%6,%7}, {%8,%9}, {%0,%1,%2,%3};"
      : "+f"(c[0]), "+f"(c[1]), "+f"(c[2]), "+f"(c[3])
      : "r"(a[0]), "r"(a[1]), "r"(a[2]), "r"(a[3]), "r"(b[0]), "r"(b[1]));
}
DEVI uint32_t packh2(float lo, float hi) {
  uint32_t d;
  asm("cvt.rn.f16x2.f32 %0, %1, %2;" : "=r"(d) : "f"(hi), "f"(lo));
  return d;
}
DEVI int ld_acq(const int* p) {
  int v;
  asm volatile("ld.acquire.gpu.global.b32 %0, [%1];" : "=r"(v) : "l"(p));
  return v;
}
DEVI int atom_add_rel(int* p, int v) {
  int o;
  asm volatile("atom.release.gpu.global.add.s32 %0, [%1], %2;"
               : "=r"(o) : "l"(p), "r"(v) : "memory");
  return o;
}
DEVI void wait_consume(int* f, int thresh, int tid) {
  if (tid == 0) {
    while (ld_acq(f) < thresh) __nanosleep(128);
    const int old = atomicAdd(f, 1);
    if (old == 2 * thresh - 1) atomicExch(f, 0);
  }
  __syncthreads();
}
DEVI uint4 cvt8(float4 a, float4 b) {
  uint4 u;
  u.x = packh2(a.x, a.y);
  u.y = packh2(a.z, a.w);
  u.z = packh2(b.x, b.y);
  u.w = packh2(b.z, b.w);
  return u;
}

// ---- single fused kernel: bulk cvt prologue + grid barrier + GEMM + scan ----
// 128 threads, 4 warps 2x2, warp tile 64x64, kc-pipelined fragments, 2 CTAs/SM
// (256 CTAs <= 296 residency slots -> grid barrier is safe).
__global__ void __launch_bounds__(128, 2)
li_kernel(const float4* __restrict__ Xf, const float4* __restrict__ Wf,
          const float* __restrict__ bias, const float* __restrict__ decay,
          float* __restrict__ out) {
  extern __shared__ __align__(16) char dsm[];
  const uint32_t sbase = s2u(dsm);

  const int tid = threadIdx.x;
  const int wid = tid >> 5;
  const int lane = tid & 31;
  const int bb = blockIdx.x >> 3;
  const int o0 = (blockIdx.x & 7) * TO;

  // ---------------- prologue: cooperative fp32 -> fp16 bulk conversion ------
  {
    uint4* xo = reinterpret_cast<uint4*>(g_Xh);
    uint4* wo = reinterpret_cast<uint4*>(g_Wh);
    // X: 8388608 float4 total -> 16384 uint4 outputs per CTA (contiguous)
    const size_t xob = (size_t)blockIdx.x * 16384 + (size_t)tid;
#pragma unroll 4
    for (int it = 0; it < 128; ++it) {
      const size_t oi = xob + (size_t)it * 128;
      xo[oi] = cvt8(Xf[2 * oi], Xf[2 * oi + 1]);
    }
    // W: 262144 float4 total -> 512 uint4 outputs per CTA
    const size_t wob = (size_t)blockIdx.x * 512 + (size_t)tid;
#pragma unroll
    for (int it = 0; it < 4; ++it) {
      const size_t oi = wob + (size_t)it * 128;
      wo[oi] = cvt8(Wf[2 * oi], Wf[2 * oi + 1]);
    }
    __threadfence();
    __syncthreads();
    if (tid == 0) atom_add_rel(&g_arr, 1);
    wait_consume(&g_arr, 256, tid);  // grid-wide: all conversion visible
  }

  // ---- scan state: every thread owns one o-channel ----
  const float dcy = decay[o0 + tid];
  const float omd = 1.0f - dcy;
  const float bo = bias[o0 + tid];
  float u = 0.f;

  // ---- cp.async constants: 16 chunks of 16B per thread ----
  const int lr = tid >> 3;
  const int lc = tid & 7;
  const uint32_t sw_off = (uint32_t)lr * 128 + (uint32_t)((lc ^ (lr & 7)) << 4);
  const __half* Wg = g_Wh + (size_t)(o0 + lr) * IN + lc * 8;
  const __half* Xg0 = g_Xh + ((size_t)bb * T + lr) * IN + lc * 8;

  // ---- mma per-thread constants ----
  const int warp_m = wid >> 1, warp_n = wid & 1;
  const int r = lane & 7;
  const int khA = lane >> 4;
  const int khB = (lane >> 3) & 1;
  const uint32_t aBase =
      (uint32_t)(warp_m * 64 + ((lane >> 3) & 1) * 8 + r) * 128;
  const uint32_t bBase =
      (uint32_t)(TT * 128) +
      (uint32_t)(warp_n * 64 + ((lane >> 4) << 3) + r) * 128;

  float acc[4][8][4];

  auto load_slab = [&](int g) {
    const int t0 = (g >> 4) * TT;
    const int k0 = (g & 15) * BKH;
    const uint32_t sb = sbase + (uint32_t)(g & 1) * STAGE_BYTES;
    const __half* Xg = Xg0 + (size_t)t0 * IN + k0;
    const __half* Ws = Wg + k0;
#pragma unroll
    for (int i = 0; i < 8; ++i)
      cp16(sb + sw_off + (uint32_t)i * 2048, Xg + (size_t)i * 16 * IN);
#pragma unroll
    for (int i = 0; i < 8; ++i)
      cp16(sb + (uint32_t)(TT * 128) + sw_off + (uint32_t)i * 2048,
           Ws + (size_t)i * 16 * IN);
  };

  int g = 0;
  load_slab(0);
  cp_commit();

  for (int tile = 0; tile < TILES; ++tile) {
#pragma unroll
    for (int mf = 0; mf < 4; ++mf)
#pragma unroll
      for (int nf = 0; nf < 8; ++nf)
#pragma unroll
        for (int j = 0; j < 4; ++j) acc[mf][nf][j] = 0.f;

    for (int ks = 0; ks < SLABS; ++ks) {
      cp_wait0();
      __syncthreads();
      const uint32_t sb = sbase + (uint32_t)(g & 1) * STAGE_BYTES;

      // ---- kc-pipelined fragment loads + MMAs ----
      uint32_t A[2][4][4], Bf[2][4][4];
      {
        const uint32_t swA = (uint32_t)((khA ^ r) << 4);
        const uint32_t swB = (uint32_t)((khB ^ r) << 4);
#pragma unroll
        for (int mf = 0; mf < 4; ++mf)
          ldsm4(A[0][mf], sb + aBase + (uint32_t)mf * 2048 + swA);
#pragma unroll
        for (int p = 0; p < 4; ++p)
          ldsm4(Bf[0][p], sb + bBase + (uint32_t)p * 2048 + swB);
      }
      if (g + 1 < G) {
        load_slab(g + 1);
        cp_commit();
      }
#pragma unroll
      for (int kc = 0; kc < 4; ++kc) {
        const int pb = kc & 1;
        if (kc < 3) {
          const uint32_t swA = (uint32_t)(((2 * (kc + 1) + khA) ^ r) << 4);
          const uint32_t swB = (uint32_t)(((2 * (kc + 1) + khB) ^ r) << 4);
#pragma unroll
          for (int mf = 0; mf < 4; ++mf)
            ldsm4(A[pb ^ 1][mf], sb + aBase + (uint32_t)mf * 2048 + swA);
#pragma unroll
          for (int p = 0; p < 4; ++p)
            ldsm4(Bf[pb ^ 1][p], sb + bBase + (uint32_t)p * 2048 + swB);
        }
#pragma unroll
        for (int mf = 0; mf < 4; ++mf)
#pragma unroll
          for (int nf = 0; nf < 8; ++nf)
            mma16(acc[mf][nf], A[pb][mf], &Bf[pb][nf >> 1][(nf & 1) * 2]);
      }
      ++g;
    }

    // ---- epilogue: fragments -> fp16 staging [t][o] ----
    unsigned* stg_u = reinterpret_cast<unsigned*>(dsm + STAGING_OFF);
#pragma unroll
    for (int mf = 0; mf < 4; ++mf)
#pragma unroll
      for (int nf = 0; nf < 8; ++nf) {
        const int row = warp_m * 64 + mf * 16 + (lane >> 2);
        const int col = warp_n * 64 + nf * 8 + 2 * (lane & 3);
        stg_u[(row * STG_STRIDE + col) >> 1] =
            packh2(acc[mf][nf][0], acc[mf][nf][1]);
        stg_u[((row + 8) * STG_STRIDE + col) >> 1] =
            packh2(acc[mf][nf][2], acc[mf][nf][3]);
      }
    __syncthreads();

    // ---- fused leaky-integrator scan; carry u persists across tiles ----
    {
      const __half* sh = reinterpret_cast<const __half*>(dsm + STAGING_OFF);
      float* ob = out + ((size_t)bb * T + tile * TT) * OUT + o0 + tid;
#pragma unroll 8
      for (int t = 0; t < TT; ++t) {
        const float x = __half2float(sh[t * STG_STRIDE + tid]) + bo;
        u = fmaf(dcy, u, omd * x);
        ob[(size_t)t * OUT] = u;
      }
    }
  }
}

}  // namespace li

extern "C" void kernel_launch(void* const* d_in, const int* in_sizes, int n_in,
                              void* d_out, int out_size) {
  const float* X = (const float*)d_in[0];      // [B,T,IN]
  const float* W = (const float*)d_in[1];      // [OUT,IN]
  const float* bias = (const float*)d_in[2];   // [OUT]
  const float* decay = (const float*)d_in[3];  // [OUT]
  float* out = (float*)d_out;                  // [B,T,OUT]

  static bool init = false;
  if (!init) {
    cudaFuncSetAttribute(li::li_kernel,
                         cudaFuncAttributeMaxDynamicSharedMemorySize,
                         li::SMEM_DYN);
    init = true;
  }
  li::li_kernel<<<li::B * (li::OUT / li::TO), 128, li::SMEM_DYN>>>(
      (const float4*)X, (const float4*)W, bias, decay, out);
}

// round 12
// speedup vs baseline: 1.9411x; 1.0377x over previous
#include <cuda_runtime.h>
#include <cuda_fp16.h>
#include <cstdint>
#include <cstddef>

#define DEVI static __device__ __forceinline__

namespace li {

constexpr int B = 32, T = 1024, IN = 1024, OUT = 1024;
constexpr int TT = 128;                 // time rows per tile (GEMM M)
constexpr int TO = 128;                 // out cols per CTA   (GEMM N)
constexpr int BKH = 64;                 // halves per K slab (= one 128B row)
constexpr int SLABS = IN / BKH;         // 16
constexpr int TILES = T / TT;           // 8
constexpr int G = TILES * SLABS;        // 128 slabs per GEMM CTA

constexpr int GEMM_CTAS = 256;
constexpr int CVT_CTAS = 40;
constexpr int GRID = GEMM_CTAS + CVT_CTAS;  // 296 = 148 SMs x 2 -> all resident

constexpr int STAGE_BYTES = (TT + TO) * 128;   // 32 KB (X 16K + W 16K, fp16)
constexpr int STG_STRIDE = 136;                // halves; conflict-free
constexpr int STAGING_OFF = 2 * STAGE_BYTES;   // 65536
constexpr int SMEM_DYN = STAGING_OFF + TT * STG_STRIDE * 2;  // 100352

// uint4 geometry of the fp16 X scratch
constexpr int XU4_PER_BT = TT * IN / 8;        // 16384 per (batch,tile)
constexpr int XU4_PER_B = T * IN / 8;          // 131072 per batch
constexpr int XU4_PER_TILE = B * XU4_PER_BT;   // 524288 per tile
constexpr int WU4 = OUT * IN / 8;              // 131072

__device__ __align__(16) __half g_Xh[(size_t)B * T * IN];   // 64MB scratch
__device__ __align__(16) __half g_Wh[(size_t)OUT * IN];     // 2MB scratch
__device__ int g_pro;        // prologue: 296 arrive + 296 consume (592 ops)
__device__ int g_tf[TILES];  // per tile: 40 arrive + 256 consume (296 ops)

DEVI uint32_t s2u(const void* p) {
  uint32_t a;
  asm("{ .reg .u64 t; cvta.to.shared.u64 t, %1; cvt.u32.u64 %0, t; }"
      : "=r"(a) : "l"(p));
  return a;
}
DEVI void cp16(uint32_t s, const void* g) {
  asm volatile("cp.async.cg.shared.global [%0], [%1], 16;" :: "r"(s), "l"(g)
               : "memory");
}
DEVI void cp_commit() { asm volatile("cp.async.commit_group;" ::: "memory"); }
DEVI void cp_wait0() { asm volatile("cp.async.wait_group 0;" ::: "memory"); }

DEVI void ldsm4(uint32_t* r, uint32_t a) {
  asm volatile("ldmatrix.sync.aligned.m8n8.x4.shared.b16 {%0,%1,%2,%3}, [%4];"
               : "=r"(r[0]), "=r"(r[1]), "=r"(r[2]), "=r"(r[3]) : "r"(a));
}
DEVI void mma16(float* c, const uint32_t* a, const uint32_t* b) {
  asm volatile(
      "mma.sync.aligned.m16n8k16.row.col.f32.f16.f16.f32 "
      "{%0,%1,%2,%3}, {%4,%5,%6,%7}, {%8,%9}, {%0,%1,%2,%3};"
      : "+f"(c[0]), "+f"(c[1]), "+f"(c[2]), "+f"(c[3])
      : "r"(a[0]), "r"(a[1]), "r"(a[2]), "r"(a[3]), "r"(b[0]), "r"(b[1]));
}
DEVI uint32_t packh2(float lo, float hi) {
  uint32_t d;
  asm("cvt.rn.f16x2.f32 %0, %1, %2;" : "=r"(d) : "f"(hi), "f"(lo));
  return d;
}
DEVI int ld_acq(const int* p) {
  int v;
  asm volatile("ld.acquire.gpu.global.b32 %0, [%1];" : "=r"(v) : "l"(p));
  return v;
}
DEVI void arrive_rel(int* p) {
  int o;
  asm volatile("atom.release.gpu.global.add.s32 %0, [%1], 1;"
               : "=r"(o) : "l"(p) : "memory");
}
// poll >= thresh, then consume-increment; op #total resets to 0 for replays
DEVI void wait_consume(int* f, int thresh, int total, int tid) {
  if (tid == 0) {
    while (ld_acq(f) < thresh) __nanosleep(128);
    const int old = atomicAdd(f, 1);
    if (old == total - 1) atomicExch(f, 0);
  }
  __syncthreads();
}
DEVI uint4 cvt8(float4 a, float4 b) {
  uint4 u;
  u.x = packh2(a.x, a.y);
  u.y = packh2(a.z, a.w);
  u.z = packh2(b.x, b.y);
  u.w = packh2(b.z, b.w);
  return u;
}

// ---- one kernel, two roles: 256 GEMM CTAs + 40 converter CTAs ---------------
__global__ void __launch_bounds__(128, 2)
li_kernel(const float4* __restrict__ Xf, const float4* __restrict__ Wf,
          const float* __restrict__ bias, const float* __restrict__ decay,
          float* __restrict__ out) {
  extern __shared__ __align__(16) char dsm[];
  const uint32_t sbase = s2u(dsm);
  const int tid = threadIdx.x;
  uint4* xo = reinterpret_cast<uint4*>(g_Xh);
  uint4* wo = reinterpret_cast<uint4*>(g_Wh);

  // ---------- cooperative prologue (all 296 CTAs): convert W + X tile 0 -----
  {
    constexpr int TOTAL0 = WU4 + XU4_PER_TILE;  // 655360 uint4
    constexpr int STRIDE0 = GRID * 128;         // 37888
    for (int idx = blockIdx.x * 128 + tid; idx < TOTAL0; idx += STRIDE0) {
      if (idx < WU4) {
        wo[idx] = cvt8(Wf[2 * (size_t)idx], Wf[2 * (size_t)idx + 1]);
      } else {
        const int j = idx - WU4;
        const size_t gi = (size_t)(j >> 14) * XU4_PER_B + (size_t)(j & 16383);
        xo[gi] = cvt8(Xf[2 * gi], Xf[2 * gi + 1]);
      }
    }
    __threadfence();
    __syncthreads();
    if (tid == 0) arrive_rel(&g_pro);
    wait_consume(&g_pro, GRID, 2 * GRID, tid);
  }

  // ---------------- converter role: stream tiles 1..7 into g_Xh -------------
  if (blockIdx.x >= GEMM_CTAS) {
    const int base = (blockIdx.x - GEMM_CTAS) * 128 + tid;
    for (int tile = 1; tile < TILES; ++tile) {
      const int toff = tile * XU4_PER_BT;
#pragma unroll 4
      for (int j = base; j < XU4_PER_TILE; j += CVT_CTAS * 128) {
        const size_t gi =
            (size_t)(j >> 14) * XU4_PER_B + (size_t)toff + (size_t)(j & 16383);
        xo[gi] = cvt8(Xf[2 * gi], Xf[2 * gi + 1]);
      }
      __threadfence();
      __syncthreads();
      if (tid == 0) arrive_rel(&g_tf[tile]);
    }
    return;
  }

  // ---------------- GEMM role (blockIdx < 256): R8 pipeline -----------------
  const int wid = tid >> 5;
  const int lane = tid & 31;
  const int bb = blockIdx.x >> 3;
  const int o0 = (blockIdx.x & 7) * TO;

  const float dcy = decay[o0 + tid];
  const float omd = 1.0f - dcy;
  const float bo = bias[o0 + tid];
  float u = 0.f;

  const int lr = tid >> 3;
  const int lc = tid & 7;
  const uint32_t sw_off = (uint32_t)lr * 128 + (uint32_t)((lc ^ (lr & 7)) << 4);
  const __half* Wg = g_Wh + (size_t)(o0 + lr) * IN + lc * 8;
  const __half* Xg0 = g_Xh + ((size_t)bb * T + lr) * IN + lc * 8;

  const int warp_m = wid >> 1, warp_n = wid & 1;
  const int r = lane & 7;
  const int khA = lane >> 4;
  const int khB = (lane >> 3) & 1;
  const uint32_t aBase =
      (uint32_t)(warp_m * 64 + ((lane >> 3) & 1) * 8 + r) * 128;
  const uint32_t bBase =
      (uint32_t)(TT * 128) +
      (uint32_t)(warp_n * 64 + ((lane >> 4) << 3) + r) * 128;

  float acc[4][8][4];

  auto load_slab = [&](int g) {
    const int t0 = (g >> 4) * TT;
    const int k0 = (g & 15) * BKH;
    const uint32_t sb = sbase + (uint32_t)(g & 1) * STAGE_BYTES;
    const __half* Xg = Xg0 + (size_t)t0 * IN + k0;
    const __half* Ws = Wg + k0;
#pragma unroll
    for (int i = 0; i < 8; ++i)
      cp16(sb + sw_off + (uint32_t)i * 2048, Xg + (size_t)i * 16 * IN);
#pragma unroll
    for (int i = 0; i < 8; ++i)
      cp16(sb + (uint32_t)(TT * 128) + sw_off + (uint32_t)i * 2048,
           Ws + (size_t)i * 16 * IN);
  };

  int g = 0;
  load_slab(0);
  cp_commit();

  for (int tile = 0; tile < TILES; ++tile) {
#pragma unroll
    for (int mf = 0; mf < 4; ++mf)
#pragma unroll
      for (int nf = 0; nf < 8; ++nf)
#pragma unroll
        for (int j = 0; j < 4; ++j) acc[mf][nf][j] = 0.f;

    for (int ks = 0; ks < SLABS; ++ks) {
      cp_wait0();
      __syncthreads();
      const uint32_t sb = sbase + (uint32_t)(g & 1) * STAGE_BYTES;

      // preload kc=0 fragments
      uint32_t A[2][4][4], Bf[2][4][4];
      {
        const uint32_t swA = (uint32_t)((khA ^ r) << 4);
        const uint32_t swB = (uint32_t)((khB ^ r) << 4);
#pragma unroll
        for (int mf = 0; mf < 4; ++mf)
          ldsm4(A[0][mf], sb + aBase + (uint32_t)mf * 2048 + swA);
#pragma unroll
        for (int p = 0; p < 4; ++p)
          ldsm4(Bf[0][p], sb + bBase + (uint32_t)p * 2048 + swB);
      }
      if (g + 1 < G) {
        if (((g + 1) & 15) == 0)  // next slab opens a new time-tile: gate it
          wait_consume(&g_tf[(g + 1) >> 4], CVT_CTAS, CVT_CTAS + GEMM_CTAS,
                       tid);
        load_slab(g + 1);
        cp_commit();
      }
#pragma unroll
      for (int kc = 0; kc < 4; ++kc) {
        const int pb = kc & 1;
        if (kc < 3) {
          const uint32_t swA = (uint32_t)(((2 * (kc + 1) + khA) ^ r) << 4);
          const uint32_t swB = (uint32_t)(((2 * (kc + 1) + khB) ^ r) << 4);
#pragma unroll
          for (int mf = 0; mf < 4; ++mf)
            ldsm4(A[pb ^ 1][mf], sb + aBase + (uint32_t)mf * 2048 + swA);
#pragma unroll
          for (int p = 0; p < 4; ++p)
            ldsm4(Bf[pb ^ 1][p], sb + bBase + (uint32_t)p * 2048 + swB);
        }
#pragma unroll
        for (int mf = 0; mf < 4; ++mf)
#pragma unroll
          for (int nf = 0; nf < 8; ++nf)
            mma16(acc[mf][nf], A[pb][mf], &Bf[pb][nf >> 1][(nf & 1) * 2]);
      }
      ++g;
    }

    // ---- epilogue: fragments -> fp16 staging [t][o] ----
    unsigned* stg_u = reinterpret_cast<unsigned*>(dsm + STAGING_OFF);
#pragma unroll
    for (int mf = 0; mf < 4; ++mf)
#pragma unroll
      for (int nf = 0; nf < 8; ++nf) {
        const int row = warp_m * 64 + mf * 16 + (lane >> 2);
        const int col = warp_n * 64 + nf * 8 + 2 * (lane & 3);
        stg_u[(row * STG_STRIDE + col) >> 1] =
            packh2(acc[mf][nf][0], acc[mf][nf][1]);
        stg_u[((row + 8) * STG_STRIDE + col) >> 1] =
            packh2(acc[mf][nf][2], acc[mf][nf][3]);
      }
    __syncthreads();

    // ---- fused leaky-integrator scan; carry u persists across tiles ----
    {
      const __half* sh = reinterpret_cast<const __half*>(dsm + STAGING_OFF);
      float* ob = out + ((size_t)bb * T + tile * TT) * OUT + o0 + tid;
#pragma unroll 8
      for (int t = 0; t < TT; ++t) {
        const float x = __half2float(sh[t * STG_STRIDE + tid]) + bo;
        u = fmaf(dcy, u, omd * x);
        ob[(size_t)t * OUT] = u;
      }
    }
  }
}

}  // namespace li

extern "C" void kernel_launch(void* const* d_in, const int* in_sizes, int n_in,
                              void* d_out, int out_size) {
  const float* X = (const float*)d_in[0];      // [B,T,IN]
  const float* W = (const float*)d_in[1];      // [OUT,IN]
  const float* bias = (const float*)d_in[2];   // [OUT]
  const float* decay = (const float*)d_in[3];  // [OUT]
  float* out = (float*)d_out;                  // [B,T,OUT]

  static bool init = false;
  if (!init) {
    cudaFuncSetAttribute(li::li_kernel,
                         cudaFuncAttributeMaxDynamicSharedMemorySize,
                         li::SMEM_DYN);
    init = true;
  }
  li::li_kernel<<<li::GRID, 128, li::SMEM_DYN>>>(
      (const float4*)X, (const float4*)W, bias, decay, out);
}